// round 14
// baseline (speedup 1.0000x reference)
#include <cuda_runtime.h>
#include <cuda_bf16.h>
#include <cuda_fp16.h>
#include <math.h>
#include <stdint.h>

#define BSZ 256
#define SLEN 512
#define HDIM 1024
#define EDIM 300
#define VOC 32000
#define KX  (EDIM + HDIM + HDIM)   // 2348
#define KXP 2352                   // 147*16 = 3*784
#define EH  (EDIM + HDIM)

__device__ __nv_bfloat16 g_Xhi[BSZ * KXP];
__device__ __nv_bfloat16 g_Xlo[BSZ * KXP];
__device__ __nv_bfloat16 g_Whi[HDIM * KXP];
__device__ __nv_bfloat16 g_Wlo[HDIM * KXP];
__device__ __half g_Ah[BSZ * HDIM];
__device__ float g_part[3][BSZ][HDIM];
__device__ float g_ctx[2][BSZ][HDIM];
__device__ float g_en[BSZ][SLEN];
__device__ float2 g_md[2][BSZ];
__device__ int g_cnt_b[BSZ];      // zero-init; self-resetting
__device__ int g_cnt_rt[64];      // zero-init; self-resetting

extern __shared__ char dynsm[];

// ---------------------------------------------------------------------------
// helpers
// ---------------------------------------------------------------------------
__device__ __forceinline__ uint32_t s2u(const void* p) {
    return (uint32_t)__cvta_generic_to_shared(p);
}
__device__ __forceinline__ void cp_async16(void* smem_dst, const void* gmem_src) {
    uint32_t s = s2u(smem_dst);
    asm volatile("cp.async.cg.shared.global [%0], [%1], 16;\n" :: "r"(s), "l"(gmem_src));
}
__device__ __forceinline__ void cp_commit() { asm volatile("cp.async.commit_group;\n"); }
template<int N> __device__ __forceinline__ void cp_wait() {
    asm volatile("cp.async.wait_group %0;\n" :: "n"(N) : "memory");
}
__device__ __forceinline__ void ldsm4(uint32_t* r, uint32_t a) {
    asm volatile("ldmatrix.sync.aligned.m8n8.x4.shared.b16 {%0,%1,%2,%3}, [%4];"
                 : "=r"(r[0]), "=r"(r[1]), "=r"(r[2]), "=r"(r[3]) : "r"(a));
}
__device__ __forceinline__ void ldsm2(uint32_t* r, uint32_t a) {
    asm volatile("ldmatrix.sync.aligned.m8n8.x2.shared.b16 {%0,%1}, [%2];"
                 : "=r"(r[0]), "=r"(r[1]) : "r"(a));
}
__device__ __forceinline__ void mma_bf16(float* c, const uint32_t* a, const uint32_t* b) {
    asm volatile(
        "mma.sync.aligned.m16n8k16.row.col.f32.bf16.bf16.f32 "
        "{%0,%1,%2,%3}, {%4,%5,%6,%7}, {%8,%9}, {%0,%1,%2,%3};"
        : "+f"(c[0]), "+f"(c[1]), "+f"(c[2]), "+f"(c[3])
        : "r"(a[0]), "r"(a[1]), "r"(a[2]), "r"(a[3]), "r"(b[0]), "r"(b[1]));
}
__device__ __forceinline__ void mma_f16(float* c, const uint32_t* a, const uint32_t* b) {
    asm volatile(
        "mma.sync.aligned.m16n8k16.row.col.f32.f16.f16.f32 "
        "{%0,%1,%2,%3}, {%4,%5,%6,%7}, {%8,%9}, {%0,%1,%2,%3};"
        : "+f"(c[0]), "+f"(c[1]), "+f"(c[2]), "+f"(c[3])
        : "r"(a[0]), "r"(a[1]), "r"(a[2]), "r"(a[3]), "r"(b[0]), "r"(b[1]));
}
union BF4 { __nv_bfloat16 h[4]; uint2 u; };
union HF4 { __half h[4]; uint2 u; };
__device__ __forceinline__ void split4v(const float4 v, uint2& hi, uint2& lo) {
    BF4 H, L;
    H.h[0] = __float2bfloat16(v.x); L.h[0] = __float2bfloat16(v.x - __bfloat162float(H.h[0]));
    H.h[1] = __float2bfloat16(v.y); L.h[1] = __float2bfloat16(v.y - __bfloat162float(H.h[1]));
    H.h[2] = __float2bfloat16(v.z); L.h[2] = __float2bfloat16(v.z - __bfloat162float(H.h[2]));
    H.h[3] = __float2bfloat16(v.w); L.h[3] = __float2bfloat16(v.w - __bfloat162float(H.h[3]));
    hi = H.u; lo = L.u;
}

// ---------------------------------------------------------------------------
// Kernel 1b: pack weights -> bf16 hi/lo (standalone, proven best in R10)
// ---------------------------------------------------------------------------
__global__ __launch_bounds__(256)
void pack_weights(const float* __restrict__ W_ih,
                  const float* __restrict__ W_hh)
{
    const int n = blockIdx.x;
    const float* src_ih = W_ih + (size_t)n * EH;
    const float* src_hh = W_hh + (size_t)n * HDIM;
    __nv_bfloat16* dh = g_Whi + (size_t)n * KXP;
    __nv_bfloat16* dl = g_Wlo + (size_t)n * KXP;
    for (int k = threadIdx.x; k < KXP; k += 256) {
        float v = 0.f;
        if (k < EH)           v = src_ih[k];
        else if (k < KX)      v = src_hh[k - EH];
        const __nv_bfloat16 H = __float2bfloat16(v);
        dh[k] = H;
        dl[k] = __float2bfloat16(v - __bfloat162float(H));
    }
}

// ---------------------------------------------------------------------------
// Kernel 1: attention halves (R10) + fused merge (last CTA per batch merges).
// grid = BSZ*2. 256 threads = 8 warps; warp w owns seq c*8+w.
// ---------------------------------------------------------------------------
#define HSTAGES 32   // 256 seq / 8
__global__ __launch_bounds__(256)
void attention_half(const float* __restrict__ hid,
                    const float* __restrict__ enc,
                    const int* __restrict__ idx,
                    const float* __restrict__ emb_table,
                    float* __restrict__ attn_out)
{
    float* tile = (float*)dynsm;          // 3 x 8192 floats
    __shared__ float2 wmd[8];
    __shared__ int s_merge;

    const int b = blockIdx.x >> 1;
    const int half = blockIdx.x & 1;
    const int t = threadIdx.x;
    const int warp = t >> 5;
    const int lane = t & 31;

    const float4* enc4 = (const float4*)(enc + (size_t)b * SLEN * HDIM + (size_t)half * 256 * HDIM);
    const float4* hrow = (const float4*)(hid + (size_t)b * HDIM);

    float4 h4[8];
    #pragma unroll
    for (int j = 0; j < 8; ++j) h4[j] = hrow[lane + 32 * j];

    #pragma unroll
    for (int st = 0; st < 2; ++st) {
        #pragma unroll
        for (int i = 0; i < 8; ++i)
            cp_async16(&tile[st * 8192 + i * HDIM + t * 4], &enc4[(st * 8 + i) * 256 + t]);
        cp_commit();
    }

    float4 ctx[8];
    #pragma unroll
    for (int j = 0; j < 8; ++j) ctx[j] = make_float4(0.f, 0.f, 0.f, 0.f);
    float m = -1e30f, d = 0.f;

    for (int c = 0; c < HSTAGES; ++c) {
        cp_wait<1>();
        __syncthreads();

        if (c + 2 < HSTAGES) {
            float* nxt = tile + ((c + 2) % 3) * 8192;
            #pragma unroll
            for (int i = 0; i < 8; ++i)
                cp_async16(&nxt[i * HDIM + t * 4], &enc4[(size_t)((c + 2) * 8 + i) * 256 + t]);
        }
        cp_commit();

        const float4* row = (const float4*)(tile + (c % 3) * 8192 + warp * HDIM);
        float4 e4[8];
        float part = 0.f;
        #pragma unroll
        for (int j = 0; j < 8; ++j) {
            e4[j] = row[lane + 32 * j];
            part += e4[j].x * h4[j].x + e4[j].y * h4[j].y
                  + e4[j].z * h4[j].z + e4[j].w * h4[j].w;
        }
        #pragma unroll
        for (int o = 16; o > 0; o >>= 1)
            part += __shfl_xor_sync(0xffffffffu, part, o);
        const float en = part;

        const float nm = fmaxf(m, en);
        const float f = __expf(m - nm);
        const float p = __expf(en - nm);
        d = d * f + p;
        m = nm;
        #pragma unroll
        for (int j = 0; j < 8; ++j) {
            ctx[j].x = ctx[j].x * f + p * e4[j].x;
            ctx[j].y = ctx[j].y * f + p * e4[j].y;
            ctx[j].z = ctx[j].z * f + p * e4[j].z;
            ctx[j].w = ctx[j].w * f + p * e4[j].w;
        }
        if (lane == 0) g_en[b][half * 256 + c * 8 + warp] = en;
    }

    // merge 8 per-warp partials (scratch = slot 0)
    __syncthreads();
    float* scratch = tile;
    #pragma unroll
    for (int j = 0; j < 8; ++j)
        ((float4*)(scratch + warp * HDIM))[lane + 32 * j] = ctx[j];
    if (lane == 0) wmd[warp] = make_float2(m, d);
    __syncthreads();

    float M = -1e30f;
    #pragma unroll
    for (int w = 0; w < 8; ++w) M = fmaxf(M, wmd[w].x);
    float fw[8], D = 0.f;
    #pragma unroll
    for (int w = 0; w < 8; ++w) { fw[w] = __expf(wmd[w].x - M); D += fw[w] * wmd[w].y; }

    float4 acc = make_float4(0.f, 0.f, 0.f, 0.f);
    #pragma unroll
    for (int w = 0; w < 8; ++w) {
        const float4 v = ((const float4*)(scratch + w * HDIM))[t];
        acc.x += fw[w] * v.x; acc.y += fw[w] * v.y;
        acc.z += fw[w] * v.z; acc.w += fw[w] * v.w;
    }
    ((float4*)&g_ctx[half][b][0])[t] = acc;
    if (t == 0) g_md[half][b] = make_float2(M, D);

    // ---- fused cross-CTA merge: second arriver for this batch does it ----
    __syncthreads();
    if (t == 0) {
        __threadfence();
        const int old = atomicAdd(&g_cnt_b[b], 1);
        s_merge = (old == 1);
        if (old == 1) g_cnt_b[b] = 0;   // reset for next graph replay
    }
    __syncthreads();
    if (!s_merge) return;
    __threadfence();

    const float2 md0 = g_md[0][b];
    const float2 md1 = g_md[1][b];
    const float mm = fmaxf(md0.x, md1.x);
    const float f0 = __expf(md0.x - mm), f1 = __expf(md1.x - mm);
    const float dd = md0.y * f0 + md1.y * f1;
    const float inv = 1.f / dd;

    __nv_bfloat16* Xh = g_Xhi + (size_t)b * KXP;
    __nv_bfloat16* Xl = g_Xlo + (size_t)b * KXP;

    const float4 c0 = ((const float4*)&g_ctx[0][b][0])[t];
    const float4 c1 = ((const float4*)&g_ctx[1][b][0])[t];
    float4 cc;
    cc.x = (c0.x * f0 + c1.x * f1) * inv;
    cc.y = (c0.y * f0 + c1.y * f1) * inv;
    cc.z = (c0.z * f0 + c1.z * f1) * inv;
    cc.w = (c0.w * f0 + c1.w * f1) * inv;
    uint2 hi, lo;
    split4v(cc, hi, lo);
    *(uint2*)(Xh + EDIM + t * 4) = hi;
    *(uint2*)(Xl + EDIM + t * 4) = lo;

    const float4 hh = hrow[t];
    split4v(hh, hi, lo);
    *(uint2*)(Xh + EDIM + HDIM + t * 4) = hi;
    *(uint2*)(Xl + EDIM + HDIM + t * 4) = lo;

    const int ci = idx[b];
    for (int j = t; j < EDIM; j += 256) {
        const float v = emb_table[(size_t)ci * EDIM + j];
        const __nv_bfloat16 H = __float2bfloat16(v);
        Xh[j] = H;
        Xl[j] = __float2bfloat16(v - __bfloat162float(H));
    }
    if (t < 4) { Xh[KX + t] = __float2bfloat16(0.f); Xl[KX + t] = __float2bfloat16(0.f); }

    for (int s = t; s < SLEN; s += 256)
        attn_out[(size_t)b * SLEN + s] = __expf(g_en[b][s] - mm) * inv;
}

// ---------------------------------------------------------------------------
// Kernel 2: RNN split-K(3) mma (R10) + fused finish (third arriver per tile).
// grid (16, 4, 3). 49 iters per CTA.
// ---------------------------------------------------------------------------
#define R_STG 4096
#define R_BOFF 12288
#define R_SMEM 24576
#define KCH 784   // KXP/3

__global__ __launch_bounds__(128, 4)
void rnn_mma(const float* __restrict__ b_ih,
             const float* __restrict__ b_hh,
             float* __restrict__ hn)
{
    __shared__ int s_fin;
    const uint32_t smb = s2u(dynsm);
    const int tid = threadIdx.x, lane = tid & 31, warp = tid >> 5;
    const int m0 = blockIdx.y * 64;
    const int n0 = blockIdx.x * 64;
    const int kc = blockIdx.z;
    const int kbase = kc * KCH;
    const int wm = (warp >> 1) * 32;
    const int wn = (warp & 1) * 32;

    const int crow = tid >> 1, chalf = tid & 1;
    const uint32_t cdst = (uint32_t)(crow * 32 + ((chalf * 16) ^ (((crow >> 2) & 1) << 4)));
    const __nv_bfloat16* Asrc_h = g_Xhi + (size_t)(m0 + crow) * KXP + kbase + chalf * 8;
    const __nv_bfloat16* Asrc_l = g_Xlo + (size_t)(m0 + crow) * KXP + kbase + chalf * 8;
    const __nv_bfloat16* Bsrc_h = g_Whi + (size_t)(n0 + crow) * KXP + kbase + chalf * 8;
    const __nv_bfloat16* Bsrc_l = g_Wlo + (size_t)(n0 + crow) * KXP + kbase + chalf * 8;

    const int lr = lane & 7, lq = (lane >> 3) & 1, lh = lane >> 4;
    uint32_t aoff[2], boff[4];
    #pragma unroll
    for (int mf = 0; mf < 2; ++mf) {
        const int row = wm + mf * 16 + lr + lq * 8;
        aoff[mf] = (uint32_t)(row * 32 + ((lh * 16) ^ (((row >> 2) & 1) << 4)));
    }
    #pragma unroll
    for (int nf = 0; nf < 4; ++nf) {
        const int row = wn + nf * 8 + lr;
        boff[nf] = (uint32_t)(row * 32 + ((lq * 16) ^ (((row >> 2) & 1) << 4)));
    }

    float c[2][4][4] = {};
    const int NS = KCH / 16;   // 49

    #pragma unroll
    for (int st = 0; st < 2; ++st) {
        char* ab = dynsm + st * R_STG;
        char* bb = dynsm + R_BOFF + st * R_STG;
        cp_async16(ab + cdst,        Asrc_h + st * 16);
        cp_async16(ab + 2048 + cdst, Asrc_l + st * 16);
        cp_async16(bb + cdst,        Bsrc_h + st * 16);
        cp_async16(bb + 2048 + cdst, Bsrc_l + st * 16);
        cp_commit();
    }

    for (int s = 0; s < NS; ++s) {
        if (s + 2 < NS) {
            char* ab = dynsm + ((s + 2) % 3) * R_STG;
            char* bb = dynsm + R_BOFF + ((s + 2) % 3) * R_STG;
            cp_async16(ab + cdst,        Asrc_h + (s + 2) * 16);
            cp_async16(ab + 2048 + cdst, Asrc_l + (s + 2) * 16);
            cp_async16(bb + cdst,        Bsrc_h + (s + 2) * 16);
            cp_async16(bb + 2048 + cdst, Bsrc_l + (s + 2) * 16);
        }
        cp_commit();
        cp_wait<2>();
        __syncthreads();

        const uint32_t Ah = smb + (s % 3) * R_STG;
        const uint32_t Al = Ah + 2048;
        const uint32_t Bh = smb + R_BOFF + (s % 3) * R_STG;
        const uint32_t Bl = Bh + 2048;

        uint32_t bh[4][2], bl[4][2];
        #pragma unroll
        for (int nf = 0; nf < 4; ++nf) {
            ldsm2(bh[nf], Bh + boff[nf]);
            ldsm2(bl[nf], Bl + boff[nf]);
        }
        #pragma unroll
        for (int mf = 0; mf < 2; ++mf) {
            uint32_t ah[4], al[4];
            ldsm4(ah, Ah + aoff[mf]);
            ldsm4(al, Al + aoff[mf]);
            #pragma unroll
            for (int nf = 0; nf < 4; ++nf) {
                mma_bf16(c[mf][nf], ah, bh[nf]);
                mma_bf16(c[mf][nf], ah, bl[nf]);
                mma_bf16(c[mf][nf], al, bh[nf]);
            }
        }
        __syncthreads();
    }

    #pragma unroll
    for (int mf = 0; mf < 2; ++mf) {
        #pragma unroll
        for (int nf = 0; nf < 4; ++nf) {
            const int n = n0 + wn + nf * 8 + (lane & 3) * 2;
            #pragma unroll
            for (int rr = 0; rr < 2; ++rr) {
                const int m = m0 + wm + mf * 16 + (lane >> 2) + rr * 8;
                *(float2*)&g_part[kc][m][n] =
                    make_float2(c[mf][nf][rr * 2 + 0], c[mf][nf][rr * 2 + 1]);
            }
        }
    }

    // ---- fused finish: third arriver for this 64x64 tile reduces it ----
    __syncthreads();
    if (tid == 0) {
        __threadfence();
        const int old = atomicAdd(&g_cnt_rt[blockIdx.y * 16 + blockIdx.x], 1);
        s_fin = (old == 2);
        if (old == 2) g_cnt_rt[blockIdx.y * 16 + blockIdx.x] = 0;
    }
    __syncthreads();
    if (!s_fin) return;
    __threadfence();

    const int n = n0 + (tid & 15) * 4;
    const float4 bi = *(const float4*)(b_ih + n);
    const float4 bb = *(const float4*)(b_hh + n);
    #pragma unroll
    for (int i = 0; i < 8; ++i) {
        const int m = m0 + (tid >> 4) + i * 8;
        const float4 p0 = *(const float4*)&g_part[0][m][n];
        const float4 p1 = *(const float4*)&g_part[1][m][n];
        const float4 p2 = *(const float4*)&g_part[2][m][n];
        float4 o;
        o.x = tanhf(p0.x + p1.x + p2.x + bi.x + bb.x);
        o.y = tanhf(p0.y + p1.y + p2.y + bi.y + bb.y);
        o.z = tanhf(p0.z + p1.z + p2.z + bi.z + bb.z);
        o.w = tanhf(p0.w + p1.w + p2.w + bi.w + bb.w);
        *(float4*)(hn + (size_t)m * HDIM + n) = o;
        HF4 H;
        H.h[0] = __float2half_rn(o.x);
        H.h[1] = __float2half_rn(o.y);
        H.h[2] = __float2half_rn(o.z);
        H.h[3] = __float2half_rn(o.w);
        *(uint2*)(g_Ah + (size_t)m * HDIM + n) = H.u;
    }
}

// ---------------------------------------------------------------------------
// Kernel 3: logits, fp16 x fp16, k32 per iteration (exact R10 version).
// ---------------------------------------------------------------------------
#define LA_STG 8192
#define LB_OFF 24576
#define LB_STG 4096
#define L_SMEM 32768

__global__ __launch_bounds__(128, 4)
void logits_mma(const __half* __restrict__ Ah,
                const float* __restrict__ Wf,
                const float* __restrict__ bf,
                float* __restrict__ Cout)
{
    const uint32_t smb = s2u(dynsm);
    const int tid = threadIdx.x, lane = tid & 31, warp = tid >> 5;
    const int m0 = blockIdx.x * 128;
    const int n0 = blockIdx.y * 64;
    const int wm = (warp >> 1) * 64;
    const int wn = (warp & 1) * 32;

    int arow[4], acol[4]; uint32_t adst[4];
    #pragma unroll
    for (int i = 0; i < 4; ++i) {
        const int f = i * 128 + tid;
        arow[i] = f >> 2;
        const int c16 = f & 3;
        acol[i] = c16 * 8;
        adst[i] = (uint32_t)(arow[i] * 64 + ((c16 ^ ((arow[i] >> 1) & 3)) << 4));
    }
    int brow[2], bcol[2]; uint32_t bdst[2];
    #pragma unroll
    for (int i = 0; i < 2; ++i) {
        const int f = i * 128 + tid;
        brow[i] = f >> 2;
        const int c16 = f & 3;
        bcol[i] = c16 * 8;
        bdst[i] = (uint32_t)(brow[i] * 64 + ((c16 ^ ((brow[i] >> 1) & 3)) << 4));
    }

    const int lr = lane & 7, lq = (lane >> 3) & 1, lh = lane >> 4;
    uint32_t aoff[4][2], boff[4];
    #pragma unroll
    for (int mf = 0; mf < 4; ++mf) {
        const int row = wm + mf * 16 + lr + lq * 8;
        #pragma unroll
        for (int kk = 0; kk < 2; ++kk)
            aoff[mf][kk] = (uint32_t)(row * 64 + (((kk * 2 + lh) ^ ((row >> 1) & 3)) << 4));
    }
    #pragma unroll
    for (int nf = 0; nf < 4; ++nf) {
        const int row = wn + nf * 8 + (lane & 7);
        const int g = lane >> 3;
        boff[nf] = (uint32_t)(row * 64 + ((g ^ ((row >> 1) & 3)) << 4));
    }

    float c[4][4][4] = {};

    float4 rb[2][2];
    #pragma unroll
    for (int i = 0; i < 2; ++i) {
        rb[i][0] = *(const float4*)(Wf + (size_t)(n0 + brow[i]) * HDIM + bcol[i]);
        rb[i][1] = *(const float4*)(Wf + (size_t)(n0 + brow[i]) * HDIM + bcol[i] + 4);
    }
    #pragma unroll
    for (int st = 0; st < 2; ++st) {
        char* base = dynsm + st * LA_STG;
        #pragma unroll
        for (int i = 0; i < 4; ++i)
            cp_async16(base + adst[i], Ah + (size_t)(m0 + arow[i]) * HDIM + st * 32 + acol[i]);
        cp_commit();
    }
    #pragma unroll
    for (int i = 0; i < 2; ++i) {
        HF4 v0, v1;
        v0.h[0] = __float2half_rn(rb[i][0].x); v0.h[1] = __float2half_rn(rb[i][0].y);
        v0.h[2] = __float2half_rn(rb[i][0].z); v0.h[3] = __float2half_rn(rb[i][0].w);
        v1.h[0] = __float2half_rn(rb[i][1].x); v1.h[1] = __float2half_rn(rb[i][1].y);
        v1.h[2] = __float2half_rn(rb[i][1].z); v1.h[3] = __float2half_rn(rb[i][1].w);
        *(uint4*)(dynsm + LB_OFF + bdst[i]) = make_uint4(v0.u.x, v0.u.y, v1.u.x, v1.u.y);
    }

    const int NS = HDIM / 32;   // 32
    for (int s = 0; s < NS; ++s) {
        const bool more = (s + 1 < NS);
        if (more) {
            #pragma unroll
            for (int i = 0; i < 2; ++i) {
                rb[i][0] = *(const float4*)(Wf + (size_t)(n0 + brow[i]) * HDIM + (s + 1) * 32 + bcol[i]);
                rb[i][1] = *(const float4*)(Wf + (size_t)(n0 + brow[i]) * HDIM + (s + 1) * 32 + bcol[i] + 4);
            }
        }
        cp_wait<1>();
        __syncthreads();

        if (s + 2 < NS) {
            char* base = dynsm + ((s + 2) % 3) * LA_STG;
            #pragma unroll
            for (int i = 0; i < 4; ++i)
                cp_async16(base + adst[i], Ah + (size_t)(m0 + arow[i]) * HDIM + (s + 2) * 32 + acol[i]);
        }
        cp_commit();

        if (more) {
            char* bb = dynsm + LB_OFF + ((s + 1) & 1) * LB_STG;
            #pragma unroll
            for (int i = 0; i < 2; ++i) {
                HF4 v0, v1;
                v0.h[0] = __float2half_rn(rb[i][0].x); v0.h[1] = __float2half_rn(rb[i][0].y);
                v0.h[2] = __float2half_rn(rb[i][0].z); v0.h[3] = __float2half_rn(rb[i][0].w);
                v1.h[0] = __float2half_rn(rb[i][1].x); v1.h[1] = __float2half_rn(rb[i][1].y);
                v1.h[2] = __float2half_rn(rb[i][1].z); v1.h[3] = __float2half_rn(rb[i][1].w);
                *(uint4*)(bb + bdst[i]) = make_uint4(v0.u.x, v0.u.y, v1.u.x, v1.u.y);
            }
        }

        const uint32_t Asm = smb + (s % 3) * LA_STG;
        const uint32_t Bsm = smb + LB_OFF + (s & 1) * LB_STG;

        uint32_t bq[4][4];
        #pragma unroll
        for (int nf = 0; nf < 4; ++nf)
            ldsm4(bq[nf], Bsm + boff[nf]);
        #pragma unroll
        for (int mf = 0; mf < 4; ++mf) {
            uint32_t aq0[4], aq1[4];
            ldsm4(aq0, Asm + aoff[mf][0]);
            ldsm4(aq1, Asm + aoff[mf][1]);
            #pragma unroll
            for (int nf = 0; nf < 4; ++nf) {
                mma_f16(c[mf][nf], aq0, &bq[nf][0]);
                mma_f16(c[mf][nf], aq1, &bq[nf][2]);
            }
        }
    }

    #pragma unroll
    for (int mf = 0; mf < 4; ++mf) {
        const int m = m0 + wm + mf * 16 + (lane >> 2);
        #pragma unroll
        for (int nf = 0; nf < 4; ++nf) {
            const int n = n0 + wn + nf * 8 + (lane & 3) * 2;
            const float b0 = bf[n], b1 = bf[n + 1];
            float2 o0 = make_float2(c[mf][nf][0] + b0, c[mf][nf][1] + b1);
            float2 o1 = make_float2(c[mf][nf][2] + b0, c[mf][nf][3] + b1);
            *(float2*)(Cout + (size_t)m * VOC + n) = o0;
            *(float2*)(Cout + (size_t)(m + 8) * VOC + n) = o1;
        }
    }
}

// ---------------------------------------------------------------------------
// Launch
// ---------------------------------------------------------------------------
extern "C" void kernel_launch(void* const* d_in, const int* in_sizes, int n_in,
                              void* d_out, int out_size)
{
    const int*   idx   = (const int*)d_in[0];
    const float* hid   = (const float*)d_in[1];
    const float* enc   = (const float*)d_in[2];
    const float* emb   = (const float*)d_in[3];
    const float* W_ih  = (const float*)d_in[4];
    const float* b_ih  = (const float*)d_in[5];
    const float* W_hh  = (const float*)d_in[6];
    const float* b_hh  = (const float*)d_in[7];
    const float* fc_W  = (const float*)d_in[8];
    const float* fc_b  = (const float*)d_in[9];

    float* out    = (float*)d_out;
    float* logits = out;
    float* hn     = out + (size_t)BSZ * VOC;
    float* attn   = out + (size_t)BSZ * VOC + (size_t)BSZ * HDIM;

    __half* Ah;
    cudaGetSymbolAddress((void**)&Ah, g_Ah);

    const int attn_smem = 3 * 8192 * 4;   // 96KB ring

    cudaFuncSetAttribute(attention_half, cudaFuncAttributeMaxDynamicSharedMemorySize, attn_smem);
    cudaFuncSetAttribute(rnn_mma,        cudaFuncAttributeMaxDynamicSharedMemorySize, R_SMEM);
    cudaFuncSetAttribute(logits_mma,     cudaFuncAttributeMaxDynamicSharedMemorySize, L_SMEM);

    pack_weights<<<HDIM, 256>>>(W_ih, W_hh);
    attention_half<<<BSZ * 2, 256, attn_smem>>>(hid, enc, idx, emb, attn);
    rnn_mma<<<dim3(HDIM / 64, BSZ / 64, 3), 128, R_SMEM>>>(b_ih, b_hh, hn);
    logits_mma<<<dim3(BSZ / 128, VOC / 64), 128, L_SMEM>>>(Ah, fc_W, fc_b, logits);
}

// round 15
// speedup vs baseline: 1.1568x; 1.1568x over previous
#include <cuda_runtime.h>
#include <cuda_bf16.h>
#include <cuda_fp16.h>
#include <math.h>
#include <stdint.h>

#define BSZ 256
#define SLEN 512
#define HDIM 1024
#define EDIM 300
#define VOC 32000
#define KX  (EDIM + HDIM + HDIM)   // 2348
#define KXP 2352                   // 147*16 = 3*784
#define EH  (EDIM + HDIM)

__device__ __nv_bfloat16 g_Xhi[BSZ * KXP];
__device__ __nv_bfloat16 g_Xlo[BSZ * KXP];
__device__ __nv_bfloat16 g_Whi[HDIM * KXP];
__device__ __nv_bfloat16 g_Wlo[HDIM * KXP];
__device__ __half g_Ah[BSZ * HDIM];
__device__ float g_part[3][BSZ][HDIM];
__device__ float g_ctx[2][BSZ][HDIM];
__device__ float g_en[BSZ][SLEN];
__device__ float2 g_md[2][BSZ];

extern __shared__ char dynsm[];

// ---------------------------------------------------------------------------
// helpers
// ---------------------------------------------------------------------------
__device__ __forceinline__ uint32_t s2u(const void* p) {
    return (uint32_t)__cvta_generic_to_shared(p);
}
__device__ __forceinline__ void cp_async16(void* smem_dst, const void* gmem_src) {
    uint32_t s = s2u(smem_dst);
    asm volatile("cp.async.cg.shared.global [%0], [%1], 16;\n" :: "r"(s), "l"(gmem_src));
}
__device__ __forceinline__ void cp_commit() { asm volatile("cp.async.commit_group;\n"); }
template<int N> __device__ __forceinline__ void cp_wait() {
    asm volatile("cp.async.wait_group %0;\n" :: "n"(N) : "memory");
}
__device__ __forceinline__ void ldsm4(uint32_t* r, uint32_t a) {
    asm volatile("ldmatrix.sync.aligned.m8n8.x4.shared.b16 {%0,%1,%2,%3}, [%4];"
                 : "=r"(r[0]), "=r"(r[1]), "=r"(r[2]), "=r"(r[3]) : "r"(a));
}
__device__ __forceinline__ void ldsm2(uint32_t* r, uint32_t a) {
    asm volatile("ldmatrix.sync.aligned.m8n8.x2.shared.b16 {%0,%1}, [%2];"
                 : "=r"(r[0]), "=r"(r[1]) : "r"(a));
}
__device__ __forceinline__ void mma_bf16(float* c, const uint32_t* a, const uint32_t* b) {
    asm volatile(
        "mma.sync.aligned.m16n8k16.row.col.f32.bf16.bf16.f32 "
        "{%0,%1,%2,%3}, {%4,%5,%6,%7}, {%8,%9}, {%0,%1,%2,%3};"
        : "+f"(c[0]), "+f"(c[1]), "+f"(c[2]), "+f"(c[3])
        : "r"(a[0]), "r"(a[1]), "r"(a[2]), "r"(a[3]), "r"(b[0]), "r"(b[1]));
}
__device__ __forceinline__ void mma_f16(float* c, const uint32_t* a, const uint32_t* b) {
    asm volatile(
        "mma.sync.aligned.m16n8k16.row.col.f32.f16.f16.f32 "
        "{%0,%1,%2,%3}, {%4,%5,%6,%7}, {%8,%9}, {%0,%1,%2,%3};"
        : "+f"(c[0]), "+f"(c[1]), "+f"(c[2]), "+f"(c[3])
        : "r"(a[0]), "r"(a[1]), "r"(a[2]), "r"(a[3]), "r"(b[0]), "r"(b[1]));
}
union BF4 { __nv_bfloat16 h[4]; uint2 u; };
union HF4 { __half h[4]; uint2 u; };
__device__ __forceinline__ void split4v(const float4 v, uint2& hi, uint2& lo) {
    BF4 H, L;
    H.h[0] = __float2bfloat16(v.x); L.h[0] = __float2bfloat16(v.x - __bfloat162float(H.h[0]));
    H.h[1] = __float2bfloat16(v.y); L.h[1] = __float2bfloat16(v.y - __bfloat162float(H.h[1]));
    H.h[2] = __float2bfloat16(v.z); L.h[2] = __float2bfloat16(v.z - __bfloat162float(H.h[2]));
    H.h[3] = __float2bfloat16(v.w); L.h[3] = __float2bfloat16(v.w - __bfloat162float(H.h[3]));
    hi = H.u; lo = L.u;
}

// ---------------------------------------------------------------------------
// Kernel 1b: pack weights -> bf16 hi/lo (runs on parallel graph branch)
// ---------------------------------------------------------------------------
__global__ __launch_bounds__(256)
void pack_weights(const float* __restrict__ W_ih,
                  const float* __restrict__ W_hh)
{
    const int n = blockIdx.x;
    const float* src_ih = W_ih + (size_t)n * EH;
    const float* src_hh = W_hh + (size_t)n * HDIM;
    __nv_bfloat16* dh = g_Whi + (size_t)n * KXP;
    __nv_bfloat16* dl = g_Wlo + (size_t)n * KXP;
    for (int k = threadIdx.x; k < KXP; k += 256) {
        float v = 0.f;
        if (k < EH)           v = src_ih[k];
        else if (k < KX)      v = src_hh[k - EH];
        const __nv_bfloat16 H = __float2bfloat16(v);
        dh[k] = H;
        dl[k] = __float2bfloat16(v - __bfloat162float(H));
    }
}

// ---------------------------------------------------------------------------
// Kernel 1: attention halves (exact R10).
// ---------------------------------------------------------------------------
#define HSTAGES 32
__global__ __launch_bounds__(256)
void attention_half(const float* __restrict__ hid,
                    const float* __restrict__ enc)
{
    float* tile = (float*)dynsm;
    __shared__ float2 wmd[8];

    const int b = blockIdx.x >> 1;
    const int half = blockIdx.x & 1;
    const int t = threadIdx.x;
    const int warp = t >> 5;
    const int lane = t & 31;

    const float4* enc4 = (const float4*)(enc + (size_t)b * SLEN * HDIM + (size_t)half * 256 * HDIM);
    const float4* hrow = (const float4*)(hid + (size_t)b * HDIM);

    float4 h4[8];
    #pragma unroll
    for (int j = 0; j < 8; ++j) h4[j] = hrow[lane + 32 * j];

    #pragma unroll
    for (int st = 0; st < 2; ++st) {
        #pragma unroll
        for (int i = 0; i < 8; ++i)
            cp_async16(&tile[st * 8192 + i * HDIM + t * 4], &enc4[(st * 8 + i) * 256 + t]);
        cp_commit();
    }

    float4 ctx[8];
    #pragma unroll
    for (int j = 0; j < 8; ++j) ctx[j] = make_float4(0.f, 0.f, 0.f, 0.f);
    float m = -1e30f, d = 0.f;

    for (int c = 0; c < HSTAGES; ++c) {
        cp_wait<1>();
        __syncthreads();

        if (c + 2 < HSTAGES) {
            float* nxt = tile + ((c + 2) % 3) * 8192;
            #pragma unroll
            for (int i = 0; i < 8; ++i)
                cp_async16(&nxt[i * HDIM + t * 4], &enc4[(size_t)((c + 2) * 8 + i) * 256 + t]);
        }
        cp_commit();

        const float4* row = (const float4*)(tile + (c % 3) * 8192 + warp * HDIM);
        float4 e4[8];
        float part = 0.f;
        #pragma unroll
        for (int j = 0; j < 8; ++j) {
            e4[j] = row[lane + 32 * j];
            part += e4[j].x * h4[j].x + e4[j].y * h4[j].y
                  + e4[j].z * h4[j].z + e4[j].w * h4[j].w;
        }
        #pragma unroll
        for (int o = 16; o > 0; o >>= 1)
            part += __shfl_xor_sync(0xffffffffu, part, o);
        const float en = part;

        const float nm = fmaxf(m, en);
        const float f = __expf(m - nm);
        const float p = __expf(en - nm);
        d = d * f + p;
        m = nm;
        #pragma unroll
        for (int j = 0; j < 8; ++j) {
            ctx[j].x = ctx[j].x * f + p * e4[j].x;
            ctx[j].y = ctx[j].y * f + p * e4[j].y;
            ctx[j].z = ctx[j].z * f + p * e4[j].z;
            ctx[j].w = ctx[j].w * f + p * e4[j].w;
        }
        if (lane == 0) g_en[b][half * 256 + c * 8 + warp] = en;
    }

    __syncthreads();
    float* scratch = tile;
    #pragma unroll
    for (int j = 0; j < 8; ++j)
        ((float4*)(scratch + warp * HDIM))[lane + 32 * j] = ctx[j];
    if (lane == 0) wmd[warp] = make_float2(m, d);
    __syncthreads();

    float M = -1e30f;
    #pragma unroll
    for (int w = 0; w < 8; ++w) M = fmaxf(M, wmd[w].x);
    float fw[8], D = 0.f;
    #pragma unroll
    for (int w = 0; w < 8; ++w) { fw[w] = __expf(wmd[w].x - M); D += fw[w] * wmd[w].y; }

    float4 acc = make_float4(0.f, 0.f, 0.f, 0.f);
    #pragma unroll
    for (int w = 0; w < 8; ++w) {
        const float4 v = ((const float4*)(scratch + w * HDIM))[t];
        acc.x += fw[w] * v.x; acc.y += fw[w] * v.y;
        acc.z += fw[w] * v.z; acc.w += fw[w] * v.w;
    }
    ((float4*)&g_ctx[half][b][0])[t] = acc;
    if (t == 0) g_md[half][b] = make_float2(M, D);
}

// ---------------------------------------------------------------------------
// Kernel 1c: merge halves (exact R10).
// ---------------------------------------------------------------------------
__global__ __launch_bounds__(256)
void attention_merge(const int* __restrict__ idx,
                     const float* __restrict__ hid,
                     const float* __restrict__ emb_table,
                     float* __restrict__ attn_out)
{
    const int b = blockIdx.x;
    const int t = threadIdx.x;

    const float2 md0 = g_md[0][b];
    const float2 md1 = g_md[1][b];
    const float m = fmaxf(md0.x, md1.x);
    const float f0 = __expf(md0.x - m), f1 = __expf(md1.x - m);
    const float dd = md0.y * f0 + md1.y * f1;
    const float inv = 1.f / dd;

    __nv_bfloat16* Xh = g_Xhi + (size_t)b * KXP;
    __nv_bfloat16* Xl = g_Xlo + (size_t)b * KXP;

    const float4 c0 = ((const float4*)&g_ctx[0][b][0])[t];
    const float4 c1 = ((const float4*)&g_ctx[1][b][0])[t];
    float4 cc;
    cc.x = (c0.x * f0 + c1.x * f1) * inv;
    cc.y = (c0.y * f0 + c1.y * f1) * inv;
    cc.z = (c0.z * f0 + c1.z * f1) * inv;
    cc.w = (c0.w * f0 + c1.w * f1) * inv;
    uint2 hi, lo;
    split4v(cc, hi, lo);
    *(uint2*)(Xh + EDIM + t * 4) = hi;
    *(uint2*)(Xl + EDIM + t * 4) = lo;

    const float4 h4 = ((const float4*)(hid + (size_t)b * HDIM))[t];
    split4v(h4, hi, lo);
    *(uint2*)(Xh + EDIM + HDIM + t * 4) = hi;
    *(uint2*)(Xl + EDIM + HDIM + t * 4) = lo;

    const int ci = idx[b];
    for (int j = t; j < EDIM; j += 256) {
        const float v = emb_table[(size_t)ci * EDIM + j];
        const __nv_bfloat16 H = __float2bfloat16(v);
        Xh[j] = H;
        Xl[j] = __float2bfloat16(v - __bfloat162float(H));
    }
    if (t < 4) { Xh[KX + t] = __float2bfloat16(0.f); Xl[KX + t] = __float2bfloat16(0.f); }

    for (int s = t; s < SLEN; s += 256)
        attn_out[(size_t)b * SLEN + s] = __expf(g_en[b][s] - m) * inv;
}

// ---------------------------------------------------------------------------
// Kernel 2: RNN split-K(3) mma (exact R10).
// ---------------------------------------------------------------------------
#define R_STG 4096
#define R_BOFF 12288
#define R_SMEM 24576
#define KCH 784

__global__ __launch_bounds__(128, 4)
void rnn_mma(float* __restrict__ dummy)
{
    const uint32_t smb = s2u(dynsm);
    const int tid = threadIdx.x, lane = tid & 31, warp = tid >> 5;
    const int m0 = blockIdx.y * 64;
    const int n0 = blockIdx.x * 64;
    const int kc = blockIdx.z;
    const int kbase = kc * KCH;
    const int wm = (warp >> 1) * 32;
    const int wn = (warp & 1) * 32;

    const int crow = tid >> 1, chalf = tid & 1;
    const uint32_t cdst = (uint32_t)(crow * 32 + ((chalf * 16) ^ (((crow >> 2) & 1) << 4)));
    const __nv_bfloat16* Asrc_h = g_Xhi + (size_t)(m0 + crow) * KXP + kbase + chalf * 8;
    const __nv_bfloat16* Asrc_l = g_Xlo + (size_t)(m0 + crow) * KXP + kbase + chalf * 8;
    const __nv_bfloat16* Bsrc_h = g_Whi + (size_t)(n0 + crow) * KXP + kbase + chalf * 8;
    const __nv_bfloat16* Bsrc_l = g_Wlo + (size_t)(n0 + crow) * KXP + kbase + chalf * 8;

    const int lr = lane & 7, lq = (lane >> 3) & 1, lh = lane >> 4;
    uint32_t aoff[2], boff[4];
    #pragma unroll
    for (int mf = 0; mf < 2; ++mf) {
        const int row = wm + mf * 16 + lr + lq * 8;
        aoff[mf] = (uint32_t)(row * 32 + ((lh * 16) ^ (((row >> 2) & 1) << 4)));
    }
    #pragma unroll
    for (int nf = 0; nf < 4; ++nf) {
        const int row = wn + nf * 8 + lr;
        boff[nf] = (uint32_t)(row * 32 + ((lq * 16) ^ (((row >> 2) & 1) << 4)));
    }

    float c[2][4][4] = {};
    const int NS = KCH / 16;

    #pragma unroll
    for (int st = 0; st < 2; ++st) {
        char* ab = dynsm + st * R_STG;
        char* bb = dynsm + R_BOFF + st * R_STG;
        cp_async16(ab + cdst,        Asrc_h + st * 16);
        cp_async16(ab + 2048 + cdst, Asrc_l + st * 16);
        cp_async16(bb + cdst,        Bsrc_h + st * 16);
        cp_async16(bb + 2048 + cdst, Bsrc_l + st * 16);
        cp_commit();
    }

    for (int s = 0; s < NS; ++s) {
        if (s + 2 < NS) {
            char* ab = dynsm + ((s + 2) % 3) * R_STG;
            char* bb = dynsm + R_BOFF + ((s + 2) % 3) * R_STG;
            cp_async16(ab + cdst,        Asrc_h + (s + 2) * 16);
            cp_async16(ab + 2048 + cdst, Asrc_l + (s + 2) * 16);
            cp_async16(bb + cdst,        Bsrc_h + (s + 2) * 16);
            cp_async16(bb + 2048 + cdst, Bsrc_l + (s + 2) * 16);
        }
        cp_commit();
        cp_wait<2>();
        __syncthreads();

        const uint32_t Ah = smb + (s % 3) * R_STG;
        const uint32_t Al = Ah + 2048;
        const uint32_t Bh = smb + R_BOFF + (s % 3) * R_STG;
        const uint32_t Bl = Bh + 2048;

        uint32_t bh[4][2], bl[4][2];
        #pragma unroll
        for (int nf = 0; nf < 4; ++nf) {
            ldsm2(bh[nf], Bh + boff[nf]);
            ldsm2(bl[nf], Bl + boff[nf]);
        }
        #pragma unroll
        for (int mf = 0; mf < 2; ++mf) {
            uint32_t ah[4], al[4];
            ldsm4(ah, Ah + aoff[mf]);
            ldsm4(al, Al + aoff[mf]);
            #pragma unroll
            for (int nf = 0; nf < 4; ++nf) {
                mma_bf16(c[mf][nf], ah, bh[nf]);
                mma_bf16(c[mf][nf], ah, bl[nf]);
                mma_bf16(c[mf][nf], al, bh[nf]);
            }
        }
        __syncthreads();
    }

    #pragma unroll
    for (int mf = 0; mf < 2; ++mf) {
        #pragma unroll
        for (int nf = 0; nf < 4; ++nf) {
            const int n = n0 + wn + nf * 8 + (lane & 3) * 2;
            #pragma unroll
            for (int rr = 0; rr < 2; ++rr) {
                const int m = m0 + wm + mf * 16 + (lane >> 2) + rr * 8;
                *(float2*)&g_part[kc][m][n] =
                    make_float2(c[mf][nf][rr * 2 + 0], c[mf][nf][rr * 2 + 1]);
            }
        }
    }
}

// ---------------------------------------------------------------------------
// Kernel 2b: reduce 3 partials, bias+tanh, hn + fp16 h_new (exact R10)
// ---------------------------------------------------------------------------
__global__ __launch_bounds__(256)
void rnn_finish(const float* __restrict__ b_ih,
                const float* __restrict__ b_hh,
                float* __restrict__ hn)
{
    const int m = blockIdx.x;
    const int n = threadIdx.x * 4;
    const float4 p0 = *(const float4*)&g_part[0][m][n];
    const float4 p1 = *(const float4*)&g_part[1][m][n];
    const float4 p2 = *(const float4*)&g_part[2][m][n];
    const float4 bi = *(const float4*)(b_ih + n);
    const float4 bh = *(const float4*)(b_hh + n);
    float4 o;
    o.x = tanhf(p0.x + p1.x + p2.x + bi.x + bh.x);
    o.y = tanhf(p0.y + p1.y + p2.y + bi.y + bh.y);
    o.z = tanhf(p0.z + p1.z + p2.z + bi.z + bh.z);
    o.w = tanhf(p0.w + p1.w + p2.w + bi.w + bh.w);
    *(float4*)(hn + (size_t)m * HDIM + n) = o;
    HF4 H;
    H.h[0] = __float2half_rn(o.x);
    H.h[1] = __float2half_rn(o.y);
    H.h[2] = __float2half_rn(o.z);
    H.h[3] = __float2half_rn(o.w);
    *(uint2*)(g_Ah + (size_t)m * HDIM + n) = H.u;
}

// ---------------------------------------------------------------------------
// Kernel 3: logits, fp16 x fp16, k32 per iteration (exact R10).
// ---------------------------------------------------------------------------
#define LA_STG 8192
#define LB_OFF 24576
#define LB_STG 4096
#define L_SMEM 32768

__global__ __launch_bounds__(128, 4)
void logits_mma(const __half* __restrict__ Ah,
                const float* __restrict__ Wf,
                const float* __restrict__ bf,
                float* __restrict__ Cout)
{
    const uint32_t smb = s2u(dynsm);
    const int tid = threadIdx.x, lane = tid & 31, warp = tid >> 5;
    const int m0 = blockIdx.x * 128;
    const int n0 = blockIdx.y * 64;
    const int wm = (warp >> 1) * 64;
    const int wn = (warp & 1) * 32;

    int arow[4], acol[4]; uint32_t adst[4];
    #pragma unroll
    for (int i = 0; i < 4; ++i) {
        const int f = i * 128 + tid;
        arow[i] = f >> 2;
        const int c16 = f & 3;
        acol[i] = c16 * 8;
        adst[i] = (uint32_t)(arow[i] * 64 + ((c16 ^ ((arow[i] >> 1) & 3)) << 4));
    }
    int brow[2], bcol[2]; uint32_t bdst[2];
    #pragma unroll
    for (int i = 0; i < 2; ++i) {
        const int f = i * 128 + tid;
        brow[i] = f >> 2;
        const int c16 = f & 3;
        bcol[i] = c16 * 8;
        bdst[i] = (uint32_t)(brow[i] * 64 + ((c16 ^ ((brow[i] >> 1) & 3)) << 4));
    }

    const int lr = lane & 7, lq = (lane >> 3) & 1, lh = lane >> 4;
    uint32_t aoff[4][2], boff[4];
    #pragma unroll
    for (int mf = 0; mf < 4; ++mf) {
        const int row = wm + mf * 16 + lr + lq * 8;
        #pragma unroll
        for (int kk = 0; kk < 2; ++kk)
            aoff[mf][kk] = (uint32_t)(row * 64 + (((kk * 2 + lh) ^ ((row >> 1) & 3)) << 4));
    }
    #pragma unroll
    for (int nf = 0; nf < 4; ++nf) {
        const int row = wn + nf * 8 + (lane & 7);
        const int g = lane >> 3;
        boff[nf] = (uint32_t)(row * 64 + ((g ^ ((row >> 1) & 3)) << 4));
    }

    float c[4][4][4] = {};

    float4 rb[2][2];
    #pragma unroll
    for (int i = 0; i < 2; ++i) {
        rb[i][0] = *(const float4*)(Wf + (size_t)(n0 + brow[i]) * HDIM + bcol[i]);
        rb[i][1] = *(const float4*)(Wf + (size_t)(n0 + brow[i]) * HDIM + bcol[i] + 4);
    }
    #pragma unroll
    for (int st = 0; st < 2; ++st) {
        char* base = dynsm + st * LA_STG;
        #pragma unroll
        for (int i = 0; i < 4; ++i)
            cp_async16(base + adst[i], Ah + (size_t)(m0 + arow[i]) * HDIM + st * 32 + acol[i]);
        cp_commit();
    }
    #pragma unroll
    for (int i = 0; i < 2; ++i) {
        HF4 v0, v1;
        v0.h[0] = __float2half_rn(rb[i][0].x); v0.h[1] = __float2half_rn(rb[i][0].y);
        v0.h[2] = __float2half_rn(rb[i][0].z); v0.h[3] = __float2half_rn(rb[i][0].w);
        v1.h[0] = __float2half_rn(rb[i][1].x); v1.h[1] = __float2half_rn(rb[i][1].y);
        v1.h[2] = __float2half_rn(rb[i][1].z); v1.h[3] = __float2half_rn(rb[i][1].w);
        *(uint4*)(dynsm + LB_OFF + bdst[i]) = make_uint4(v0.u.x, v0.u.y, v1.u.x, v1.u.y);
    }

    const int NS = HDIM / 32;
    for (int s = 0; s < NS; ++s) {
        const bool more = (s + 1 < NS);
        if (more) {
            #pragma unroll
            for (int i = 0; i < 2; ++i) {
                rb[i][0] = *(const float4*)(Wf + (size_t)(n0 + brow[i]) * HDIM + (s + 1) * 32 + bcol[i]);
                rb[i][1] = *(const float4*)(Wf + (size_t)(n0 + brow[i]) * HDIM + (s + 1) * 32 + bcol[i] + 4);
            }
        }
        cp_wait<1>();
        __syncthreads();

        if (s + 2 < NS) {
            char* base = dynsm + ((s + 2) % 3) * LA_STG;
            #pragma unroll
            for (int i = 0; i < 4; ++i)
                cp_async16(base + adst[i], Ah + (size_t)(m0 + arow[i]) * HDIM + (s + 2) * 32 + acol[i]);
        }
        cp_commit();

        if (more) {
            char* bb = dynsm + LB_OFF + ((s + 1) & 1) * LB_STG;
            #pragma unroll
            for (int i = 0; i < 2; ++i) {
                HF4 v0, v1;
                v0.h[0] = __float2half_rn(rb[i][0].x); v0.h[1] = __float2half_rn(rb[i][0].y);
                v0.h[2] = __float2half_rn(rb[i][0].z); v0.h[3] = __float2half_rn(rb[i][0].w);
                v1.h[0] = __float2half_rn(rb[i][1].x); v1.h[1] = __float2half_rn(rb[i][1].y);
                v1.h[2] = __float2half_rn(rb[i][1].z); v1.h[3] = __float2half_rn(rb[i][1].w);
                *(uint4*)(bb + bdst[i]) = make_uint4(v0.u.x, v0.u.y, v1.u.x, v1.u.y);
            }
        }

        const uint32_t Asm = smb + (s % 3) * LA_STG;
        const uint32_t Bsm = smb + LB_OFF + (s & 1) * LB_STG;

        uint32_t bq[4][4];
        #pragma unroll
        for (int nf = 0; nf < 4; ++nf)
            ldsm4(bq[nf], Bsm + boff[nf]);
        #pragma unroll
        for (int mf = 0; mf < 4; ++mf) {
            uint32_t aq0[4], aq1[4];
            ldsm4(aq0, Asm + aoff[mf][0]);
            ldsm4(aq1, Asm + aoff[mf][1]);
            #pragma unroll
            for (int nf = 0; nf < 4; ++nf) {
                mma_f16(c[mf][nf], aq0, &bq[nf][0]);
                mma_f16(c[mf][nf], aq1, &bq[nf][2]);
            }
        }
    }

    #pragma unroll
    for (int mf = 0; mf < 4; ++mf) {
        const int m = m0 + wm + mf * 16 + (lane >> 2);
        #pragma unroll
        for (int nf = 0; nf < 4; ++nf) {
            const int n = n0 + wn + nf * 8 + (lane & 3) * 2;
            const float b0 = bf[n], b1 = bf[n + 1];
            float2 o0 = make_float2(c[mf][nf][0] + b0, c[mf][nf][1] + b1);
            float2 o1 = make_float2(c[mf][nf][2] + b0, c[mf][nf][3] + b1);
            *(float2*)(Cout + (size_t)m * VOC + n) = o0;
            *(float2*)(Cout + (size_t)(m + 8) * VOC + n) = o1;
        }
    }
}

// ---------------------------------------------------------------------------
// Launch: graph fork — pack_weights runs on a parallel branch alongside
// attention (independent data), joined before rnn_mma.
// ---------------------------------------------------------------------------
extern "C" void kernel_launch(void* const* d_in, const int* in_sizes, int n_in,
                              void* d_out, int out_size)
{
    const int*   idx   = (const int*)d_in[0];
    const float* hid   = (const float*)d_in[1];
    const float* enc   = (const float*)d_in[2];
    const float* emb   = (const float*)d_in[3];
    const float* W_ih  = (const float*)d_in[4];
    const float* b_ih  = (const float*)d_in[5];
    const float* W_hh  = (const float*)d_in[6];
    const float* b_hh  = (const float*)d_in[7];
    const float* fc_W  = (const float*)d_in[8];
    const float* fc_b  = (const float*)d_in[9];

    float* out    = (float*)d_out;
    float* logits = out;
    float* hn     = out + (size_t)BSZ * VOC;
    float* attn   = out + (size_t)BSZ * VOC + (size_t)BSZ * HDIM;

    __half* Ah;
    cudaGetSymbolAddress((void**)&Ah, g_Ah);

    const int attn_smem = 3 * 8192 * 4;

    static cudaStream_t s_side = nullptr;
    static cudaEvent_t ev_fork = nullptr, ev_join = nullptr;
    static bool s_init = false;
    if (!s_init) {
        cudaStreamCreateWithFlags(&s_side, cudaStreamNonBlocking);
        cudaEventCreateWithFlags(&ev_fork, cudaEventDisableTiming);
        cudaEventCreateWithFlags(&ev_join, cudaEventDisableTiming);
        cudaFuncSetAttribute(attention_half, cudaFuncAttributeMaxDynamicSharedMemorySize, attn_smem);
        cudaFuncSetAttribute(rnn_mma,        cudaFuncAttributeMaxDynamicSharedMemorySize, R_SMEM);
        cudaFuncSetAttribute(logits_mma,     cudaFuncAttributeMaxDynamicSharedMemorySize, L_SMEM);
        s_init = true;
    }

    // fork: side branch does pack_weights concurrently with attention
    cudaEventRecord(ev_fork, 0);
    cudaStreamWaitEvent(s_side, ev_fork, 0);
    pack_weights<<<HDIM, 256, 0, s_side>>>(W_ih, W_hh);
    cudaEventRecord(ev_join, s_side);

    attention_half<<<BSZ * 2, 256, attn_smem>>>(hid, enc);
    attention_merge<<<BSZ, 256>>>(idx, hid, emb, attn);

    // join: rnn needs packed weights
    cudaStreamWaitEvent(0, ev_join, 0);
    rnn_mma<<<dim3(HDIM / 64, BSZ / 64, 3), 128, R_SMEM>>>(nullptr);
    rnn_finish<<<BSZ, 256>>>(b_ih, b_hh, hn);
    logits_mma<<<dim3(BSZ / 128, VOC / 64), 128, L_SMEM>>>(Ah, fc_W, fc_b, logits);
}

// round 16
// speedup vs baseline: 1.2333x; 1.0661x over previous
#include <cuda_runtime.h>
#include <cuda_bf16.h>
#include <cuda_fp16.h>
#include <math.h>
#include <stdint.h>

#define BSZ 256
#define SLEN 512
#define HDIM 1024
#define EDIM 300
#define VOC 32000
#define KX  (EDIM + HDIM + HDIM)   // 2348
#define KXP 2352                   // 147*16 = 3*784
#define EH  (EDIM + HDIM)

__device__ __nv_bfloat16 g_Xhi[BSZ * KXP];
__device__ __nv_bfloat16 g_Xlo[BSZ * KXP];
__device__ __nv_bfloat16 g_Whi[HDIM * KXP];
__device__ __nv_bfloat16 g_Wlo[HDIM * KXP];
__device__ __half g_Ah[BSZ * HDIM];
__device__ float g_part[3][BSZ][HDIM];
__device__ float g_ctx[2][BSZ][HDIM];
__device__ float g_en[BSZ][SLEN];
__device__ float2 g_md[2][BSZ];

extern __shared__ char dynsm[];

// ---------------------------------------------------------------------------
// helpers
// ---------------------------------------------------------------------------
__device__ __forceinline__ uint32_t s2u(const void* p) {
    return (uint32_t)__cvta_generic_to_shared(p);
}
__device__ __forceinline__ void cp_async16(void* smem_dst, const void* gmem_src) {
    uint32_t s = s2u(smem_dst);
    asm volatile("cp.async.cg.shared.global [%0], [%1], 16;\n" :: "r"(s), "l"(gmem_src));
}
__device__ __forceinline__ void cp_commit() { asm volatile("cp.async.commit_group;\n"); }
template<int N> __device__ __forceinline__ void cp_wait() {
    asm volatile("cp.async.wait_group %0;\n" :: "n"(N) : "memory");
}
__device__ __forceinline__ void ldsm4(uint32_t* r, uint32_t a) {
    asm volatile("ldmatrix.sync.aligned.m8n8.x4.shared.b16 {%0,%1,%2,%3}, [%4];"
                 : "=r"(r[0]), "=r"(r[1]), "=r"(r[2]), "=r"(r[3]) : "r"(a));
}
__device__ __forceinline__ void ldsm2(uint32_t* r, uint32_t a) {
    asm volatile("ldmatrix.sync.aligned.m8n8.x2.shared.b16 {%0,%1}, [%2];"
                 : "=r"(r[0]), "=r"(r[1]) : "r"(a));
}
__device__ __forceinline__ void mma_bf16(float* c, const uint32_t* a, const uint32_t* b) {
    asm volatile(
        "mma.sync.aligned.m16n8k16.row.col.f32.bf16.bf16.f32 "
        "{%0,%1,%2,%3}, {%4,%5,%6,%7}, {%8,%9}, {%0,%1,%2,%3};"
        : "+f"(c[0]), "+f"(c[1]), "+f"(c[2]), "+f"(c[3])
        : "r"(a[0]), "r"(a[1]), "r"(a[2]), "r"(a[3]), "r"(b[0]), "r"(b[1]));
}
__device__ __forceinline__ void mma_f16(float* c, const uint32_t* a, const uint32_t* b) {
    asm volatile(
        "mma.sync.aligned.m16n8k16.row.col.f32.f16.f16.f32 "
        "{%0,%1,%2,%3}, {%4,%5,%6,%7}, {%8,%9}, {%0,%1,%2,%3};"
        : "+f"(c[0]), "+f"(c[1]), "+f"(c[2]), "+f"(c[3])
        : "r"(a[0]), "r"(a[1]), "r"(a[2]), "r"(a[3]), "r"(b[0]), "r"(b[1]));
}
union BF4 { __nv_bfloat16 h[4]; uint2 u; };
union HF4 { __half h[4]; uint2 u; };
__device__ __forceinline__ void split4v(const float4 v, uint2& hi, uint2& lo) {
    BF4 H, L;
    H.h[0] = __float2bfloat16(v.x); L.h[0] = __float2bfloat16(v.x - __bfloat162float(H.h[0]));
    H.h[1] = __float2bfloat16(v.y); L.h[1] = __float2bfloat16(v.y - __bfloat162float(H.h[1]));
    H.h[2] = __float2bfloat16(v.z); L.h[2] = __float2bfloat16(v.z - __bfloat162float(H.h[2]));
    H.h[3] = __float2bfloat16(v.w); L.h[3] = __float2bfloat16(v.w - __bfloat162float(H.h[3]));
    hi = H.u; lo = L.u;
}

// ---------------------------------------------------------------------------
// Kernel 1b: pack weights -> bf16 hi/lo (exact R10)
// ---------------------------------------------------------------------------
__global__ __launch_bounds__(256)
void pack_weights(const float* __restrict__ W_ih,
                  const float* __restrict__ W_hh)
{
    const int n = blockIdx.x;
    const float* src_ih = W_ih + (size_t)n * EH;
    const float* src_hh = W_hh + (size_t)n * HDIM;
    __nv_bfloat16* dh = g_Whi + (size_t)n * KXP;
    __nv_bfloat16* dl = g_Wlo + (size_t)n * KXP;
    for (int k = threadIdx.x; k < KXP; k += 256) {
        float v = 0.f;
        if (k < EH)           v = src_ih[k];
        else if (k < KX)      v = src_hh[k - EH];
        const __nv_bfloat16 H = __float2bfloat16(v);
        dh[k] = H;
        dl[k] = __float2bfloat16(v - __bfloat162float(H));
    }
}

// ---------------------------------------------------------------------------
// Kernel 1: attention halves (exact R10).
// ---------------------------------------------------------------------------
#define HSTAGES 32
__global__ __launch_bounds__(256)
void attention_half(const float* __restrict__ hid,
                    const float* __restrict__ enc)
{
    float* tile = (float*)dynsm;
    __shared__ float2 wmd[8];

    const int b = blockIdx.x >> 1;
    const int half = blockIdx.x & 1;
    const int t = threadIdx.x;
    const int warp = t >> 5;
    const int lane = t & 31;

    const float4* enc4 = (const float4*)(enc + (size_t)b * SLEN * HDIM + (size_t)half * 256 * HDIM);
    const float4* hrow = (const float4*)(hid + (size_t)b * HDIM);

    float4 h4[8];
    #pragma unroll
    for (int j = 0; j < 8; ++j) h4[j] = hrow[lane + 32 * j];

    #pragma unroll
    for (int st = 0; st < 2; ++st) {
        #pragma unroll
        for (int i = 0; i < 8; ++i)
            cp_async16(&tile[st * 8192 + i * HDIM + t * 4], &enc4[(st * 8 + i) * 256 + t]);
        cp_commit();
    }

    float4 ctx[8];
    #pragma unroll
    for (int j = 0; j < 8; ++j) ctx[j] = make_float4(0.f, 0.f, 0.f, 0.f);
    float m = -1e30f, d = 0.f;

    for (int c = 0; c < HSTAGES; ++c) {
        cp_wait<1>();
        __syncthreads();

        if (c + 2 < HSTAGES) {
            float* nxt = tile + ((c + 2) % 3) * 8192;
            #pragma unroll
            for (int i = 0; i < 8; ++i)
                cp_async16(&nxt[i * HDIM + t * 4], &enc4[(size_t)((c + 2) * 8 + i) * 256 + t]);
        }
        cp_commit();

        const float4* row = (const float4*)(tile + (c % 3) * 8192 + warp * HDIM);
        float4 e4[8];
        float part = 0.f;
        #pragma unroll
        for (int j = 0; j < 8; ++j) {
            e4[j] = row[lane + 32 * j];
            part += e4[j].x * h4[j].x + e4[j].y * h4[j].y
                  + e4[j].z * h4[j].z + e4[j].w * h4[j].w;
        }
        #pragma unroll
        for (int o = 16; o > 0; o >>= 1)
            part += __shfl_xor_sync(0xffffffffu, part, o);
        const float en = part;

        const float nm = fmaxf(m, en);
        const float f = __expf(m - nm);
        const float p = __expf(en - nm);
        d = d * f + p;
        m = nm;
        #pragma unroll
        for (int j = 0; j < 8; ++j) {
            ctx[j].x = ctx[j].x * f + p * e4[j].x;
            ctx[j].y = ctx[j].y * f + p * e4[j].y;
            ctx[j].z = ctx[j].z * f + p * e4[j].z;
            ctx[j].w = ctx[j].w * f + p * e4[j].w;
        }
        if (lane == 0) g_en[b][half * 256 + c * 8 + warp] = en;
    }

    __syncthreads();
    float* scratch = tile;
    #pragma unroll
    for (int j = 0; j < 8; ++j)
        ((float4*)(scratch + warp * HDIM))[lane + 32 * j] = ctx[j];
    if (lane == 0) wmd[warp] = make_float2(m, d);
    __syncthreads();

    float M = -1e30f;
    #pragma unroll
    for (int w = 0; w < 8; ++w) M = fmaxf(M, wmd[w].x);
    float fw[8], D = 0.f;
    #pragma unroll
    for (int w = 0; w < 8; ++w) { fw[w] = __expf(wmd[w].x - M); D += fw[w] * wmd[w].y; }

    float4 acc = make_float4(0.f, 0.f, 0.f, 0.f);
    #pragma unroll
    for (int w = 0; w < 8; ++w) {
        const float4 v = ((const float4*)(scratch + w * HDIM))[t];
        acc.x += fw[w] * v.x; acc.y += fw[w] * v.y;
        acc.z += fw[w] * v.z; acc.w += fw[w] * v.w;
    }
    ((float4*)&g_ctx[half][b][0])[t] = acc;
    if (t == 0) g_md[half][b] = make_float2(M, D);
}

// ---------------------------------------------------------------------------
// Kernel 1c: merge halves (exact R10).
// ---------------------------------------------------------------------------
__global__ __launch_bounds__(256)
void attention_merge(const int* __restrict__ idx,
                     const float* __restrict__ hid,
                     const float* __restrict__ emb_table,
                     float* __restrict__ attn_out)
{
    const int b = blockIdx.x;
    const int t = threadIdx.x;

    const float2 md0 = g_md[0][b];
    const float2 md1 = g_md[1][b];
    const float m = fmaxf(md0.x, md1.x);
    const float f0 = __expf(md0.x - m), f1 = __expf(md1.x - m);
    const float dd = md0.y * f0 + md1.y * f1;
    const float inv = 1.f / dd;

    __nv_bfloat16* Xh = g_Xhi + (size_t)b * KXP;
    __nv_bfloat16* Xl = g_Xlo + (size_t)b * KXP;

    const float4 c0 = ((const float4*)&g_ctx[0][b][0])[t];
    const float4 c1 = ((const float4*)&g_ctx[1][b][0])[t];
    float4 cc;
    cc.x = (c0.x * f0 + c1.x * f1) * inv;
    cc.y = (c0.y * f0 + c1.y * f1) * inv;
    cc.z = (c0.z * f0 + c1.z * f1) * inv;
    cc.w = (c0.w * f0 + c1.w * f1) * inv;
    uint2 hi, lo;
    split4v(cc, hi, lo);
    *(uint2*)(Xh + EDIM + t * 4) = hi;
    *(uint2*)(Xl + EDIM + t * 4) = lo;

    const float4 h4 = ((const float4*)(hid + (size_t)b * HDIM))[t];
    split4v(h4, hi, lo);
    *(uint2*)(Xh + EDIM + HDIM + t * 4) = hi;
    *(uint2*)(Xl + EDIM + HDIM + t * 4) = lo;

    const int ci = idx[b];
    for (int j = t; j < EDIM; j += 256) {
        const float v = emb_table[(size_t)ci * EDIM + j];
        const __nv_bfloat16 H = __float2bfloat16(v);
        Xh[j] = H;
        Xl[j] = __float2bfloat16(v - __bfloat162float(H));
    }
    if (t < 4) { Xh[KX + t] = __float2bfloat16(0.f); Xl[KX + t] = __float2bfloat16(0.f); }

    for (int s = t; s < SLEN; s += 256)
        attn_out[(size_t)b * SLEN + s] = __expf(g_en[b][s] - m) * inv;
}

// ---------------------------------------------------------------------------
// Kernel 2: RNN split-K(3) mma (exact R10).
// ---------------------------------------------------------------------------
#define R_STG 4096
#define R_BOFF 12288
#define R_SMEM 24576
#define KCH 784

__global__ __launch_bounds__(128, 4)
void rnn_mma(float* __restrict__ dummy)
{
    const uint32_t smb = s2u(dynsm);
    const int tid = threadIdx.x, lane = tid & 31, warp = tid >> 5;
    const int m0 = blockIdx.y * 64;
    const int n0 = blockIdx.x * 64;
    const int kc = blockIdx.z;
    const int kbase = kc * KCH;
    const int wm = (warp >> 1) * 32;
    const int wn = (warp & 1) * 32;

    const int crow = tid >> 1, chalf = tid & 1;
    const uint32_t cdst = (uint32_t)(crow * 32 + ((chalf * 16) ^ (((crow >> 2) & 1) << 4)));
    const __nv_bfloat16* Asrc_h = g_Xhi + (size_t)(m0 + crow) * KXP + kbase + chalf * 8;
    const __nv_bfloat16* Asrc_l = g_Xlo + (size_t)(m0 + crow) * KXP + kbase + chalf * 8;
    const __nv_bfloat16* Bsrc_h = g_Whi + (size_t)(n0 + crow) * KXP + kbase + chalf * 8;
    const __nv_bfloat16* Bsrc_l = g_Wlo + (size_t)(n0 + crow) * KXP + kbase + chalf * 8;

    const int lr = lane & 7, lq = (lane >> 3) & 1, lh = lane >> 4;
    uint32_t aoff[2], boff[4];
    #pragma unroll
    for (int mf = 0; mf < 2; ++mf) {
        const int row = wm + mf * 16 + lr + lq * 8;
        aoff[mf] = (uint32_t)(row * 32 + ((lh * 16) ^ (((row >> 2) & 1) << 4)));
    }
    #pragma unroll
    for (int nf = 0; nf < 4; ++nf) {
        const int row = wn + nf * 8 + lr;
        boff[nf] = (uint32_t)(row * 32 + ((lq * 16) ^ (((row >> 2) & 1) << 4)));
    }

    float c[2][4][4] = {};
    const int NS = KCH / 16;

    #pragma unroll
    for (int st = 0; st < 2; ++st) {
        char* ab = dynsm + st * R_STG;
        char* bb = dynsm + R_BOFF + st * R_STG;
        cp_async16(ab + cdst,        Asrc_h + st * 16);
        cp_async16(ab + 2048 + cdst, Asrc_l + st * 16);
        cp_async16(bb + cdst,        Bsrc_h + st * 16);
        cp_async16(bb + 2048 + cdst, Bsrc_l + st * 16);
        cp_commit();
    }

    for (int s = 0; s < NS; ++s) {
        if (s + 2 < NS) {
            char* ab = dynsm + ((s + 2) % 3) * R_STG;
            char* bb = dynsm + R_BOFF + ((s + 2) % 3) * R_STG;
            cp_async16(ab + cdst,        Asrc_h + (s + 2) * 16);
            cp_async16(ab + 2048 + cdst, Asrc_l + (s + 2) * 16);
            cp_async16(bb + cdst,        Bsrc_h + (s + 2) * 16);
            cp_async16(bb + 2048 + cdst, Bsrc_l + (s + 2) * 16);
        }
        cp_commit();
        cp_wait<2>();
        __syncthreads();

        const uint32_t Ah = smb + (s % 3) * R_STG;
        const uint32_t Al = Ah + 2048;
        const uint32_t Bh = smb + R_BOFF + (s % 3) * R_STG;
        const uint32_t Bl = Bh + 2048;

        uint32_t bh[4][2], bl[4][2];
        #pragma unroll
        for (int nf = 0; nf < 4; ++nf) {
            ldsm2(bh[nf], Bh + boff[nf]);
            ldsm2(bl[nf], Bl + boff[nf]);
        }
        #pragma unroll
        for (int mf = 0; mf < 2; ++mf) {
            uint32_t ah[4], al[4];
            ldsm4(ah, Ah + aoff[mf]);
            ldsm4(al, Al + aoff[mf]);
            #pragma unroll
            for (int nf = 0; nf < 4; ++nf) {
                mma_bf16(c[mf][nf], ah, bh[nf]);
                mma_bf16(c[mf][nf], ah, bl[nf]);
                mma_bf16(c[mf][nf], al, bh[nf]);
            }
        }
        __syncthreads();
    }

    #pragma unroll
    for (int mf = 0; mf < 2; ++mf) {
        #pragma unroll
        for (int nf = 0; nf < 4; ++nf) {
            const int n = n0 + wn + nf * 8 + (lane & 3) * 2;
            #pragma unroll
            for (int rr = 0; rr < 2; ++rr) {
                const int m = m0 + wm + mf * 16 + (lane >> 2) + rr * 8;
                *(float2*)&g_part[kc][m][n] =
                    make_float2(c[mf][nf][rr * 2 + 0], c[mf][nf][rr * 2 + 1]);
            }
        }
    }
}

// ---------------------------------------------------------------------------
// Kernel 2b: reduce 3 partials, bias+tanh, hn + fp16 h_new (exact R10)
// ---------------------------------------------------------------------------
__global__ __launch_bounds__(256)
void rnn_finish(const float* __restrict__ b_ih,
                const float* __restrict__ b_hh,
                float* __restrict__ hn)
{
    const int m = blockIdx.x;
    const int n = threadIdx.x * 4;
    const float4 p0 = *(const float4*)&g_part[0][m][n];
    const float4 p1 = *(const float4*)&g_part[1][m][n];
    const float4 p2 = *(const float4*)&g_part[2][m][n];
    const float4 bi = *(const float4*)(b_ih + n);
    const float4 bh = *(const float4*)(b_hh + n);
    float4 o;
    o.x = tanhf(p0.x + p1.x + p2.x + bi.x + bh.x);
    o.y = tanhf(p0.y + p1.y + p2.y + bi.y + bh.y);
    o.z = tanhf(p0.z + p1.z + p2.z + bi.z + bh.z);
    o.w = tanhf(p0.w + p1.w + p2.w + bi.w + bh.w);
    *(float4*)(hn + (size_t)m * HDIM + n) = o;
    HF4 H;
    H.h[0] = __float2half_rn(o.x);
    H.h[1] = __float2half_rn(o.y);
    H.h[2] = __float2half_rn(o.z);
    H.h[3] = __float2half_rn(o.w);
    *(uint2*)(g_Ah + (size_t)m * HDIM + n) = H.u;
}

// ---------------------------------------------------------------------------
// Kernel 3: logits, fp16 x fp16, k32/iter. R10 layout, loop REORDERED:
// B's LDG->cvt->STS moved AFTER the MMA block so the DRAM latency of the
// fc_W load is covered by tensor work instead of stalling the warp pre-MMA.
// ---------------------------------------------------------------------------
#define LA_STG 8192
#define LB_OFF 24576
#define LB_STG 4096
#define L_SMEM 32768

__global__ __launch_bounds__(128, 4)
void logits_mma(const __half* __restrict__ Ah,
                const float* __restrict__ Wf,
                const float* __restrict__ bf,
                float* __restrict__ Cout)
{
    const uint32_t smb = s2u(dynsm);
    const int tid = threadIdx.x, lane = tid & 31, warp = tid >> 5;
    const int m0 = blockIdx.x * 128;
    const int n0 = blockIdx.y * 64;
    const int wm = (warp >> 1) * 64;
    const int wn = (warp & 1) * 32;

    int arow[4], acol[4]; uint32_t adst[4];
    #pragma unroll
    for (int i = 0; i < 4; ++i) {
        const int f = i * 128 + tid;
        arow[i] = f >> 2;
        const int c16 = f & 3;
        acol[i] = c16 * 8;
        adst[i] = (uint32_t)(arow[i] * 64 + ((c16 ^ ((arow[i] >> 1) & 3)) << 4));
    }
    int brow[2], bcol[2]; uint32_t bdst[2];
    #pragma unroll
    for (int i = 0; i < 2; ++i) {
        const int f = i * 128 + tid;
        brow[i] = f >> 2;
        const int c16 = f & 3;
        bcol[i] = c16 * 8;
        bdst[i] = (uint32_t)(brow[i] * 64 + ((c16 ^ ((brow[i] >> 1) & 3)) << 4));
    }

    const int lr = lane & 7, lq = (lane >> 3) & 1, lh = lane >> 4;
    uint32_t aoff[4][2], boff[4];
    #pragma unroll
    for (int mf = 0; mf < 4; ++mf) {
        const int row = wm + mf * 16 + lr + lq * 8;
        #pragma unroll
        for (int kk = 0; kk < 2; ++kk)
            aoff[mf][kk] = (uint32_t)(row * 64 + (((kk * 2 + lh) ^ ((row >> 1) & 3)) << 4));
    }
    #pragma unroll
    for (int nf = 0; nf < 4; ++nf) {
        const int row = wn + nf * 8 + (lane & 7);
        const int g = lane >> 3;
        boff[nf] = (uint32_t)(row * 64 + ((g ^ ((row >> 1) & 3)) << 4));
    }

    float c[4][4][4] = {};

    // prologue: B stage 0 regs->STS; A stages 0,1 cp.async
    float4 rb[2][2];
    #pragma unroll
    for (int i = 0; i < 2; ++i) {
        rb[i][0] = *(const float4*)(Wf + (size_t)(n0 + brow[i]) * HDIM + bcol[i]);
        rb[i][1] = *(const float4*)(Wf + (size_t)(n0 + brow[i]) * HDIM + bcol[i] + 4);
    }
    #pragma unroll
    for (int st = 0; st < 2; ++st) {
        char* base = dynsm + st * LA_STG;
        #pragma unroll
        for (int i = 0; i < 4; ++i)
            cp_async16(base + adst[i], Ah + (size_t)(m0 + arow[i]) * HDIM + st * 32 + acol[i]);
        cp_commit();
    }
    #pragma unroll
    for (int i = 0; i < 2; ++i) {
        HF4 v0, v1;
        v0.h[0] = __float2half_rn(rb[i][0].x); v0.h[1] = __float2half_rn(rb[i][0].y);
        v0.h[2] = __float2half_rn(rb[i][0].z); v0.h[3] = __float2half_rn(rb[i][0].w);
        v1.h[0] = __float2half_rn(rb[i][1].x); v1.h[1] = __float2half_rn(rb[i][1].y);
        v1.h[2] = __float2half_rn(rb[i][1].z); v1.h[3] = __float2half_rn(rb[i][1].w);
        *(uint4*)(dynsm + LB_OFF + bdst[i]) = make_uint4(v0.u.x, v0.u.y, v1.u.x, v1.u.y);
    }

    const int NS = HDIM / 32;   // 32
    for (int s = 0; s < NS; ++s) {
        const bool more = (s + 1 < NS);
        // issue next B loads early (latency hidden by MMA block below)
        if (more) {
            #pragma unroll
            for (int i = 0; i < 2; ++i) {
                rb[i][0] = *(const float4*)(Wf + (size_t)(n0 + brow[i]) * HDIM + (s + 1) * 32 + bcol[i]);
                rb[i][1] = *(const float4*)(Wf + (size_t)(n0 + brow[i]) * HDIM + (s + 1) * 32 + bcol[i] + 4);
            }
        }
        cp_wait<1>();
        __syncthreads();

        if (s + 2 < NS) {
            char* base = dynsm + ((s + 2) % 3) * LA_STG;
            #pragma unroll
            for (int i = 0; i < 4; ++i)
                cp_async16(base + adst[i], Ah + (size_t)(m0 + arow[i]) * HDIM + (s + 2) * 32 + acol[i]);
        }
        cp_commit();

        // compute on stage s FIRST (covers the in-flight B LDG)
        const uint32_t Asm = smb + (s % 3) * LA_STG;
        const uint32_t Bsm = smb + LB_OFF + (s & 1) * LB_STG;

        uint32_t bq[4][4];
        #pragma unroll
        for (int nf = 0; nf < 4; ++nf)
            ldsm4(bq[nf], Bsm + boff[nf]);
        #pragma unroll
        for (int mf = 0; mf < 4; ++mf) {
            uint32_t aq0[4], aq1[4];
            ldsm4(aq0, Asm + aoff[mf][0]);
            ldsm4(aq1, Asm + aoff[mf][1]);
            #pragma unroll
            for (int nf = 0; nf < 4; ++nf) {
                mma_f16(c[mf][nf], aq0, &bq[nf][0]);
                mma_f16(c[mf][nf], aq1, &bq[nf][2]);
            }
        }

        // STS of B stage s+1 AFTER the MMAs; visible after next barrier
        if (more) {
            char* bb = dynsm + LB_OFF + ((s + 1) & 1) * LB_STG;
            #pragma unroll
            for (int i = 0; i < 2; ++i) {
                HF4 v0, v1;
                v0.h[0] = __float2half_rn(rb[i][0].x); v0.h[1] = __float2half_rn(rb[i][0].y);
                v0.h[2] = __float2half_rn(rb[i][0].z); v0.h[3] = __float2half_rn(rb[i][0].w);
                v1.h[0] = __float2half_rn(rb[i][1].x); v1.h[1] = __float2half_rn(rb[i][1].y);
                v1.h[2] = __float2half_rn(rb[i][1].z); v1.h[3] = __float2half_rn(rb[i][1].w);
                *(uint4*)(bb + bdst[i]) = make_uint4(v0.u.x, v0.u.y, v1.u.x, v1.u.y);
            }
        }
    }

    #pragma unroll
    for (int mf = 0; mf < 4; ++mf) {
        const int m = m0 + wm + mf * 16 + (lane >> 2);
        #pragma unroll
        for (int nf = 0; nf < 4; ++nf) {
            const int n = n0 + wn + nf * 8 + (lane & 3) * 2;
            const float b0 = bf[n], b1 = bf[n + 1];
            float2 o0 = make_float2(c[mf][nf][0] + b0, c[mf][nf][1] + b1);
            float2 o1 = make_float2(c[mf][nf][2] + b0, c[mf][nf][3] + b1);
            *(float2*)(Cout + (size_t)m * VOC + n) = o0;
            *(float2*)(Cout + (size_t)(m + 8) * VOC + n) = o1;
        }
    }
}

// ---------------------------------------------------------------------------
// Launch (exact R10 sequence)
// ---------------------------------------------------------------------------
extern "C" void kernel_launch(void* const* d_in, const int* in_sizes, int n_in,
                              void* d_out, int out_size)
{
    const int*   idx   = (const int*)d_in[0];
    const float* hid   = (const float*)d_in[1];
    const float* enc   = (const float*)d_in[2];
    const float* emb   = (const float*)d_in[3];
    const float* W_ih  = (const float*)d_in[4];
    const float* b_ih  = (const float*)d_in[5];
    const float* W_hh  = (const float*)d_in[6];
    const float* b_hh  = (const float*)d_in[7];
    const float* fc_W  = (const float*)d_in[8];
    const float* fc_b  = (const float*)d_in[9];

    float* out    = (float*)d_out;
    float* logits = out;
    float* hn     = out + (size_t)BSZ * VOC;
    float* attn   = out + (size_t)BSZ * VOC + (size_t)BSZ * HDIM;

    __half* Ah;
    cudaGetSymbolAddress((void**)&Ah, g_Ah);

    const int attn_smem = 3 * 8192 * 4;

    cudaFuncSetAttribute(attention_half, cudaFuncAttributeMaxDynamicSharedMemorySize, attn_smem);
    cudaFuncSetAttribute(rnn_mma,        cudaFuncAttributeMaxDynamicSharedMemorySize, R_SMEM);
    cudaFuncSetAttribute(logits_mma,     cudaFuncAttributeMaxDynamicSharedMemorySize, L_SMEM);

    pack_weights<<<HDIM, 256>>>(W_ih, W_hh);
    attention_half<<<BSZ * 2, 256, attn_smem>>>(hid, enc);
    attention_merge<<<BSZ, 256>>>(idx, hid, emb, attn);
    rnn_mma<<<dim3(HDIM / 64, BSZ / 64, 3), 128, R_SMEM>>>(nullptr);
    rnn_finish<<<BSZ, 256>>>(b_ih, b_hh, hn);
    logits_mma<<<dim3(BSZ / 128, VOC / 64), 128, L_SMEM>>>(Ah, fc_W, fc_b, logits);
}